// round 6
// baseline (speedup 1.0000x reference)
#include <cuda_runtime.h>
#include <math.h>

#define BB 4
#define TT 128
#define HH 1024
#define EE 512
#define AA 512
#define VV 16000
#define SS 512
#define NB 128
#define NT 512

// ---------------- persistent device state (allocation-free scratch) ----------------
__device__ __align__(16) float d_h[2][BB][HH];          // GRU hidden, double buffered
__device__ __align__(16) float d_av[2][BB][AA];         // attention vector, double buffered
__device__ __align__(16) float d_enc_out[BB][TT][HH];   // encoder outputs (2 MB)
__device__ __align__(16) float d_P[BB][AA][TT];         // W_av_left @ enc_out  (1 MB)
__device__ __align__(16) float d_gi[TT][BB][3*HH];      // encoder input-gate preacts (6.3 MB)
__device__ float d_score[BB][TT];
__device__ float d_cval[NB][BB];
__device__ int   d_cidx[NB][BB];
__device__ unsigned d_cnt;
__device__ volatile unsigned d_gen;

__device__ __forceinline__ float wred(float v){
    #pragma unroll
    for (int o = 16; o; o >>= 1) v += __shfl_down_sync(0xffffffffu, v, o);
    return v;
}
__device__ __forceinline__ float sigm(float x){ return 1.0f / (1.0f + expf(-x)); }

// Sense-reversing grid barrier over NB co-resident blocks.
__device__ __forceinline__ void gbar(){
    __syncthreads();
    if (threadIdx.x == 0){
        __threadfence();
        unsigned gen = d_gen;
        if (atomicAdd(&d_cnt, 1u) == (unsigned)(NB - 1)){
            d_cnt = 0u;
            __threadfence();
            d_gen = gen + 1u;
        } else {
            while (d_gen == gen) { }
            __threadfence();
        }
    }
    __syncthreads();
}

__global__ __launch_bounds__(NT) void seq2seq_kernel(
    const int*   __restrict__ inputs,
    const float* __restrict__ enc_emb, const float* __restrict__ enc_Wih,
    const float* __restrict__ enc_Whh, const float* __restrict__ enc_bih,
    const float* __restrict__ enc_bhh,
    const float* __restrict__ dec_emb, const float* __restrict__ dec_Wih,
    const float* __restrict__ dec_Whh, const float* __restrict__ dec_bih,
    const float* __restrict__ dec_bhh,
    const float* __restrict__ W_av,  const float* __restrict__ b_av,
    const float* __restrict__ W_cls, const float* __restrict__ b_cls,
    float* __restrict__ out)
{
    const int tid  = threadIdx.x;
    const int bl   = blockIdx.x;
    const int w    = tid >> 5;
    const int lane = tid & 31;

    __shared__ __align__(16) float sm_av[BB*AA];   // 8 KB
    __shared__ float sm_w[BB*TT];                  // 2 KB
    __shared__ float sm_lg[BB*125];
    __shared__ float sm_g[48*BB];
    __shared__ float sm_bv[16*BB];
    __shared__ int   sm_bi[16*BB];
    __shared__ float sm_part[16];
    __shared__ int   sm_ids[BB];

    // ---- setup 0: zero recurrent state (graph replays must be deterministic) ----
    for (int i = bl*NT + tid; i < 2*BB*HH + 2*BB*AA; i += NB*NT){
        if (i < 2*BB*HH) (&d_h[0][0][0])[i] = 0.f;
        else             (&d_av[0][0][0])[i - 2*BB*HH] = 0.f;
    }

    // ---- setup A: encoder input-gate preactivations gi[t][b][row] ----
    // 3072 rows split 24 per block; warps 0..11 hold 2 W_ih rows in registers.
    {
        int r0 = bl * 24;
        if (w < 12){
            int row0 = r0 + 2*w, row1 = row0 + 1;
            float w0[16], w1[16];
            #pragma unroll
            for (int i = 0; i < 16; i++){
                w0[i] = enc_Wih[row0*EE + lane + 32*i];
                w1[i] = enc_Wih[row1*EE + lane + 32*i];
            }
            float b0 = enc_bih[row0], b1 = enc_bih[row1];
            for (int tb = 0; tb < TT*BB; tb++){
                int t = tb >> 2, b = tb & 3;
                int tok = inputs[b*TT + t];
                const float* em = enc_emb + (size_t)tok * EE;
                float a0 = 0.f, a1 = 0.f;
                #pragma unroll
                for (int i = 0; i < 16; i++){
                    float e = em[lane + 32*i];
                    a0 += w0[i]*e; a1 += w1[i]*e;
                }
                a0 = wred(a0); a1 = wred(a1);
                if (lane == 0){
                    d_gi[t][b][row0] = a0 + b0;
                    d_gi[t][b][row1] = a1 + b1;
                }
            }
        }
    }
    gbar();

    // ---- encoder scan: each block owns 8 hidden dims (all 3 gate rows) ----
    {
        int j0 = bl * 8;
        for (int t = 0; t < TT; t++){
            int cur = t & 1, nxt = cur ^ 1;
            for (int d = w; d < 24; d += 16){
                int jl = d / 3, g = d % 3;
                int row = g*HH + j0 + jl;
                const float4* Wr = (const float4*)(enc_Whh + (size_t)row * HH);
                float a[BB] = {0.f,0.f,0.f,0.f};
                #pragma unroll
                for (int i = 0; i < 8; i++){
                    int k4 = lane + 32*i;
                    float4 wv = Wr[k4];
                    #pragma unroll
                    for (int b = 0; b < BB; b++){
                        float4 hv = ((const float4*)d_h[cur][b])[k4];
                        a[b] += wv.x*hv.x + wv.y*hv.y + wv.z*hv.z + wv.w*hv.w;
                    }
                }
                #pragma unroll
                for (int b = 0; b < BB; b++){
                    float r = wred(a[b]);
                    if (lane == 0) sm_g[d*BB + b] = r + enc_bhh[row];
                }
            }
            __syncthreads();
            if (tid < 32){
                int jl = tid >> 2, b = tid & 3, j = j0 + jl;
                float gr = sm_g[(jl*3+0)*BB+b], gz = sm_g[(jl*3+1)*BB+b], gn = sm_g[(jl*3+2)*BB+b];
                float ir = d_gi[t][b][j], iz = d_gi[t][b][j+HH], inn = d_gi[t][b][j+2*HH];
                float r = sigm(ir + gr), z = sigm(iz + gz);
                float n = tanhf(inn + r*gn);
                float hp = d_h[cur][b][j];
                float hn = (1.f - z)*n + z*hp;
                d_h[nxt][b][j]    = hn;
                d_enc_out[b][t][j] = hn;
            }
            gbar();
        }
    }

    // ---- setup P: P[b][a][t] = sum_k W_av[a][k] * enc_out[b][t][k]  (left half of W_av) ----
    {
        int a = bl*4 + (w & 3);
        int q = w >> 2;
        float wa[32];
        #pragma unroll
        for (int i = 0; i < 32; i++) wa[i] = W_av[(size_t)a*2*HH + lane + 32*i];
        for (int tb = q*128; tb < q*128 + 128; tb++){
            int t = tb >> 2, b = tb & 3;
            const float* eo = d_enc_out[b][t];
            float acc = 0.f;
            #pragma unroll
            for (int i = 0; i < 32; i++) acc += wa[i] * eo[lane + 32*i];
            acc = wred(acc);
            if (lane == 0) d_P[b][a][t] = acc;
        }
    }
    gbar();

    // ---- decoder: 512 greedy steps ----
    const int base_v = bl * 125;                 // 16000 = 128 * 125
    const size_t OUT_ATT = (size_t)SS * BB * VV;

    for (int s = 0; s < SS; s++){
        int cur = s & 1, nxt = cur ^ 1;

        // combine previous step's per-block argmax candidates -> ids (first-max tie-break)
        if (w < BB){
            int b = w;
            float best = -3.4e38f; int bi = 0;
            if (s > 0){
                #pragma unroll
                for (int i = 0; i < 4; i++){
                    int q2 = lane + 32*i;
                    float v = d_cval[q2][b]; int ii = d_cidx[q2][b];
                    if (v > best || (v == best && ii < bi)){ best = v; bi = ii; }
                }
                #pragma unroll
                for (int o = 16; o; o >>= 1){
                    float ov = __shfl_xor_sync(0xffffffffu, best, o);
                    int   oi = __shfl_xor_sync(0xffffffffu, bi,   o);
                    if (ov > best || (ov == best && oi < bi)){ best = ov; bi = oi; }
                }
            }
            if (lane == 0) sm_ids[b] = (s > 0) ? bi : 0;
        }
        __syncthreads();

        // ---- phase A: GRU hidden update (block owns 8 j's; 48 warp-dots) ----
        {
            int j0 = bl * 8;
            for (int d = w; d < 48; d += 16){
                int dd = d % 24;
                int jl = dd / 3, g = dd % 3;
                int row = g*HH + j0 + jl;
                float a[BB] = {0.f,0.f,0.f,0.f};
                if (d < 24){
                    const float4* Wr = (const float4*)(dec_Wih + (size_t)row * (EE+AA));
                    const float4* em[BB];
                    #pragma unroll
                    for (int b = 0; b < BB; b++)
                        em[b] = (const float4*)(dec_emb + (size_t)sm_ids[b] * EE);
                    #pragma unroll
                    for (int i = 0; i < 8; i++){
                        int k4 = lane + 32*i;
                        float4 wv = Wr[k4];
                        #pragma unroll
                        for (int b = 0; b < BB; b++){
                            float4 xv = (k4 < 128) ? em[b][k4]
                                                   : ((const float4*)d_av[cur][b])[k4 - 128];
                            a[b] += wv.x*xv.x + wv.y*xv.y + wv.z*xv.z + wv.w*xv.w;
                        }
                    }
                    #pragma unroll
                    for (int b = 0; b < BB; b++){
                        float r = wred(a[b]);
                        if (lane == 0) sm_g[d*BB + b] = r + dec_bih[row];
                    }
                } else {
                    const float4* Wr = (const float4*)(dec_Whh + (size_t)row * HH);
                    #pragma unroll
                    for (int i = 0; i < 8; i++){
                        int k4 = lane + 32*i;
                        float4 wv = Wr[k4];
                        #pragma unroll
                        for (int b = 0; b < BB; b++){
                            float4 hv = ((const float4*)d_h[cur][b])[k4];
                            a[b] += wv.x*hv.x + wv.y*hv.y + wv.z*hv.z + wv.w*hv.w;
                        }
                    }
                    #pragma unroll
                    for (int b = 0; b < BB; b++){
                        float r = wred(a[b]);
                        if (lane == 0) sm_g[d*BB + b] = r + dec_bhh[row];
                    }
                }
            }
            __syncthreads();
            if (tid < 32){
                int jl = tid >> 2, b = tid & 3, j = bl*8 + jl;
                float ir  = sm_g[(jl*3+0)*BB+b], iz = sm_g[(jl*3+1)*BB+b], inn = sm_g[(jl*3+2)*BB+b];
                float gr  = sm_g[(24+jl*3+0)*BB+b], gz = sm_g[(24+jl*3+1)*BB+b], gn = sm_g[(24+jl*3+2)*BB+b];
                float r = sigm(ir + gr), z = sigm(iz + gz);
                float n = tanhf(inn + r*gn);
                float hp = d_h[cur][b][j];
                d_h[nxt][b][j] = (1.f - z)*n + z*hp;
            }
        }
        gbar();

        // ---- phase B1: attention scores (4 (b,t) dots per block, 4 warps per dot) ----
        {
            int q2 = w >> 2, sub = w & 3;
            int idx = bl*4 + q2;
            int b = idx >> 7, t = idx & 127;
            const float4* eo = (const float4*)d_enc_out[b][t];
            const float4* hv = (const float4*)d_h[nxt][b];
            float acc = 0.f;
            #pragma unroll
            for (int i = 0; i < 2; i++){
                int k4 = sub*64 + lane + 32*i;
                float4 a4 = eo[k4], b4 = hv[k4];
                acc += a4.x*b4.x + a4.y*b4.y + a4.z*b4.z + a4.w*b4.w;
            }
            acc = wred(acc);
            if (lane == 0) sm_part[w] = acc;
            __syncthreads();
            if (tid < 4){
                int idx2 = bl*4 + tid;
                int b2 = idx2 >> 7, t2 = idx2 & 127;
                float sc = sm_part[tid*4+0] + sm_part[tid*4+1] + sm_part[tid*4+2] + sm_part[tid*4+3];
                if (inputs[b2*TT + t2] == 0) sc = -1e30f;
                d_score[b2][t2] = sc;
            }
        }
        gbar();

        // ---- phase B2: softmax (redundant per block) + attn_vec slice via P ----
        {
            if (w < 4){
                int b = w;
                float x[4];
                float m = -1e30f;
                #pragma unroll
                for (int i = 0; i < 4; i++){ x[i] = d_score[b][lane + 32*i]; m = fmaxf(m, x[i]); }
                #pragma unroll
                for (int o = 16; o; o >>= 1) m = fmaxf(m, __shfl_xor_sync(0xffffffffu, m, o));
                float sum = 0.f;
                #pragma unroll
                for (int i = 0; i < 4; i++){ x[i] = expf(x[i] - m); sum += x[i]; }
                #pragma unroll
                for (int o = 16; o; o >>= 1) sum += __shfl_xor_sync(0xffffffffu, sum, o);
                float inv = 1.f / sum;
                #pragma unroll
                for (int i = 0; i < 4; i++) sm_w[b*TT + lane + 32*i] = x[i] * inv;
            }
            __syncthreads();
            {
                int b = w & 3, a = bl*4 + (w >> 2);
                float acc = 0.f;
                #pragma unroll
                for (int i = 0; i < 4; i++){
                    int t = lane + 32*i;
                    acc += sm_w[b*TT + t] * d_P[b][a][t];
                }
                const float4* Wr = (const float4*)(W_av + (size_t)a*2*HH + HH);
                const float4* hv = (const float4*)d_h[nxt][b];
                #pragma unroll
                for (int i = 0; i < 8; i++){
                    int k4 = lane + 32*i;
                    float4 wv = Wr[k4]; float4 h4 = hv[k4];
                    acc += wv.x*h4.x + wv.y*h4.y + wv.z*h4.z + wv.w*h4.w;
                }
                acc = wred(acc);
                if (lane == 0) d_av[nxt][b][a] = tanhf(acc + b_av[a]);
            }
            if (bl < BB && tid < TT)
                out[OUT_ATT + ((size_t)s*BB + bl)*TT + tid] = sm_w[bl*TT + tid];
        }
        gbar();

        // ---- phase C: logits (125 vocab rows per block), write + local argmax ----
        {
            for (int i = tid; i < BB*AA; i += NT) sm_av[i] = (&d_av[nxt][0][0])[i];
            __syncthreads();
            float bestv[BB] = {-3.4e38f,-3.4e38f,-3.4e38f,-3.4e38f};
            int   besti[BB] = {0,0,0,0};
            for (int r = w; r < 125; r += 16){
                int v = base_v + r;
                const float4* Wr = (const float4*)(W_cls + (size_t)v * AA);
                float a[BB] = {0.f,0.f,0.f,0.f};
                #pragma unroll
                for (int i = 0; i < 4; i++){
                    int k4 = lane + 32*i;
                    float4 wv = Wr[k4];
                    #pragma unroll
                    for (int b = 0; b < BB; b++){
                        float4 av4 = ((const float4*)(sm_av + b*AA))[k4];
                        a[b] += wv.x*av4.x + wv.y*av4.y + wv.z*av4.z + wv.w*av4.w;
                    }
                }
                #pragma unroll
                for (int b = 0; b < BB; b++){
                    float lg = wred(a[b]);
                    if (lane == 0){
                        lg += b_cls[v];
                        sm_lg[b*125 + r] = lg;
                        if (lg > bestv[b]){ bestv[b] = lg; besti[b] = v; }
                    }
                }
            }
            if (lane == 0){
                #pragma unroll
                for (int b = 0; b < BB; b++){ sm_bv[w*BB + b] = bestv[b]; sm_bi[w*BB + b] = besti[b]; }
            }
            __syncthreads();
            for (int i = tid; i < BB*125; i += NT){
                int b = i / 125, r = i % 125;
                out[((size_t)s*BB + b)*VV + base_v + r] = sm_lg[i];
            }
            if (tid < BB){
                int b = tid;
                float best = -3.4e38f; int bi = 0;
                for (int w2 = 0; w2 < 16; w2++){
                    float v = sm_bv[w2*BB + b]; int i2 = sm_bi[w2*BB + b];
                    if (v > best || (v == best && i2 < bi)){ best = v; bi = i2; }
                }
                d_cval[bl][b] = best; d_cidx[bl][b] = bi;
            }
        }
        gbar();
    }
}

extern "C" void kernel_launch(void* const* d_in, const int* in_sizes, int n_in,
                              void* d_out, int out_size)
{
    (void)in_sizes; (void)n_in; (void)out_size;
    seq2seq_kernel<<<NB, NT>>>(
        (const int*)  d_in[0],
        (const float*)d_in[1],  (const float*)d_in[2],  (const float*)d_in[3],
        (const float*)d_in[4],  (const float*)d_in[5],
        (const float*)d_in[6],  (const float*)d_in[7],  (const float*)d_in[8],
        (const float*)d_in[9],  (const float*)d_in[10],
        (const float*)d_in[11], (const float*)d_in[12],
        (const float*)d_in[13], (const float*)d_in[14],
        (float*)d_out);
}